// round 9
// baseline (speedup 1.0000x reference)
#include <cuda_runtime.h>
#include <cuda_bf16.h>
#include <math.h>
#include <stdint.h>

#define HID   256
#define NB    128
#define HW    32
#define NBLK  144            // 9 cell-slots x 16 j-slices, persistent (1/SM)
#define CSLOTS 9
#define THREADS 512          // 16 warps
#define PITCH 528            // bytes per bf16 tile row (264 bf16; 33x16B -> ldmatrix conflict-free)

// ---- smem layout (bytes) ----
#define SM_CONST 0                              // bias[64], wih[64] floats (512 B)
#define SM_A_HI  1024                           // A hi: 128 x 264 bf16 (67584 B)
#define SM_A_LO  (SM_A_HI + 128 * PITCH)
#define SM_W_HI  (SM_A_LO + 128 * PITCH)        // W hi: 64 x 264 bf16 (33792 B), rows n = jt*4+type
#define SM_W_LO  (SM_W_HI + 64 * PITCH)
#define SMEM_TOTAL (SM_W_LO + 64 * PITCH)       // 203776 B

// Cell state s, layout [cell][b][j]. 134 MB scratch.
__device__ float g_s[(size_t)HW * HW * NB * HID];
// grid barrier
__device__ int      g_bar_count;
__device__ unsigned g_bar_gen;

__device__ __forceinline__ uint32_t smem_u32(const void* p) {
    uint32_t a;
    asm("{ .reg .u64 t; cvta.to.shared.u64 t, %1; cvt.u32.u64 %0, t; }" : "=r"(a) : "l"(p));
    return a;
}
__device__ __forceinline__ float sigmoidf_(float v) { return 1.0f / (1.0f + expf(-v)); }

__device__ __forceinline__ void ldm_x4(uint32_t& r0, uint32_t& r1, uint32_t& r2, uint32_t& r3,
                                       uint32_t addr) {
    asm volatile("ldmatrix.sync.aligned.m8n8.x4.shared.b16 {%0,%1,%2,%3}, [%4];"
        : "=r"(r0), "=r"(r1), "=r"(r2), "=r"(r3) : "r"(addr));
}
__device__ __forceinline__ void mma_bf16(float* c, const uint32_t* a, uint32_t b0, uint32_t b1) {
    asm volatile(
        "mma.sync.aligned.m16n8k16.row.col.f32.bf16.bf16.f32 "
        "{%0,%1,%2,%3}, {%4,%5,%6,%7}, {%8,%9}, {%0,%1,%2,%3};"
        : "+f"(c[0]), "+f"(c[1]), "+f"(c[2]), "+f"(c[3])
        : "r"(a[0]), "r"(a[1]), "r"(a[2]), "r"(a[3]), "r"(b0), "r"(b1));
}

__device__ __forceinline__ uint32_t bf2u(__nv_bfloat162 v) {
    return *reinterpret_cast<uint32_t*>(&v);
}
// split float pair -> (hi bf16x2, lo bf16x2)
__device__ __forceinline__ void split2(float a, float b, uint32_t& hi, uint32_t& lo) {
    __nv_bfloat162 h = __floats2bfloat162_rn(a, b);
    float la = a - __low2float(h);
    float lb = b - __high2float(h);
    __nv_bfloat162 l = __floats2bfloat162_rn(la, lb);
    hi = bf2u(h); lo = bf2u(l);
}

__device__ __forceinline__ void grid_barrier() {
    __syncthreads();
    if (threadIdx.x == 0) {
        __threadfence();
        unsigned gen = *((volatile unsigned*)&g_bar_gen);
        int t = atomicAdd(&g_bar_count, 1);
        if (t == NBLK - 1) {
            g_bar_count = 0;
            __threadfence();
            atomicAdd(&g_bar_gen, 1u);
        } else {
            while (*((volatile unsigned*)&g_bar_gen) == gen) { }
        }
    }
    __syncthreads();
}

// Persistent MD-LSTM. Block = 512 threads (16 warps). Tile: M=128 batches x
// N=64 gate rows (row n = jt*4 + type) x K=256, split-precision bf16 HMMA.
// Warp (mrow, nh) computes m16 x n32. Gate types reunited via shfl.bfly.
__global__ __launch_bounds__(THREADS, 1)
void mdlstm_mma(const float* __restrict__ x,
                const float* __restrict__ w_ih,
                const float* __restrict__ w_hh,
                const float* __restrict__ bias,
                float*       __restrict__ out)
{
    extern __shared__ unsigned char smem[];
    const uint32_t smb  = smem_u32(smem);
    const int tid  = threadIdx.x;
    const int lane = tid & 31;
    const int wrp  = tid >> 5;            // 0..15
    const int mrow = wrp & 7;
    const int nh   = wrp >> 3;            // n-half: jt range nh*8..nh*8+7
    const int sb    = blockIdx.x & 15;    // j-slice
    const int cslot = blockIdx.x >> 4;    // 0..8

    // ---- one-time: W slice split into smem hi/lo, rows n = jt*4 + type ----
    {
        const int n    = tid >> 3;                 // 0..63
        const int kc   = (tid & 7) * 32;
        const int type = n & 3, jt = n >> 2;
        const int j    = sb * 16 + jt;
        const float* src = w_hh + ((size_t)(type * 256 + j) * 256 + kc);
        unsigned char* dhi = smem + SM_W_HI + n * PITCH + kc * 2;
        unsigned char* dlo = smem + SM_W_LO + n * PITCH + kc * 2;
        #pragma unroll
        for (int i = 0; i < 8; i++) {
            float4 v = *(const float4*)(src + i * 4);
            uint32_t h0, l0, h1, l1;
            split2(v.x, v.y, h0, l0);
            split2(v.z, v.w, h1, l1);
            *(uint2*)(dhi + i * 8) = make_uint2(h0, h1);
            *(uint2*)(dlo + i * 8) = make_uint2(l0, l1);
        }
    }
    if (tid < 64) {
        const int type = tid >> 4, jt = tid & 15;
        const int j = sb * 16 + jt;
        ((float*)(smem + SM_CONST))[tid]      = bias[type * 256 + j];   // sbias[type*16+jt]
        ((float*)(smem + SM_CONST))[64 + tid] = w_ih[type * 256 + j];
    }
    __syncthreads();

    // per-lane ldmatrix address components
    const int m0 = mrow * 16;
    const uint32_t a_off = (uint32_t)(m0 + (lane & 15)) * PITCH + (lane >> 4) * 16;
    const uint32_t b_off = (uint32_t)(nh * 32 + (lane & 15)) * PITCH + (lane >> 4) * 16;

    const int q  = lane & 3;
    const int rr = lane >> 2;             // 0..7
    const int p  = q & 1;                 // parity: 0 -> row rr, 1 -> row rr+8
    const int b_ep = m0 + rr + p * 8;     // epilogue batch index
    const float* sbias = (const float*)(smem + SM_CONST);
    const float* swih  = sbias + 64;

    for (int d = 0; d < 2 * HW - 1; d++) {
        const int n_d = (d < HW) ? (d + 1) : (2 * HW - 1 - d);
        const int r0  = (d > HW - 1) ? d - (HW - 1) : 0;

        for (int cell = cslot; cell < n_d; cell += CSLOTS) {
            const int r = r0 + cell, c = d - r;
            const int cell_id = r * HW + c;
            const bool has_up = (r > 0), has_left = (c > 0);

            float acc[4][4];
            #pragma unroll
            for (int f = 0; f < 4; f++)
                #pragma unroll
                for (int e = 0; e < 4; e++) acc[f][e] = 0.0f;

            if (has_up || has_left) {
                // ---- stage hsum = h_up + h_left, split -> smem A hi/lo ----
                {
                    const int bb = tid >> 2;
                    const int j0 = (tid & 3) * 64;
                    const float* pu = out + (size_t)bb * (HW * HW * HID)
                                          + (size_t)(cell_id - HW) * HID + j0;
                    const float* pl = out + (size_t)bb * (HW * HW * HID)
                                          + (size_t)(cell_id - 1) * HID + j0;
                    unsigned char* ahi = smem + SM_A_HI + bb * PITCH + j0 * 2;
                    unsigned char* alo = smem + SM_A_LO + bb * PITCH + j0 * 2;
                    #pragma unroll 8
                    for (int i = 0; i < 16; i++) {
                        float4 v = make_float4(0.f, 0.f, 0.f, 0.f);
                        if (has_up) {
                            float4 u = *(const float4*)(pu + i * 4);
                            v.x = u.x; v.y = u.y; v.z = u.z; v.w = u.w;
                        }
                        if (has_left) {
                            float4 l = *(const float4*)(pl + i * 4);
                            v.x += l.x; v.y += l.y; v.z += l.z; v.w += l.w;
                        }
                        uint32_t h0, l0, h1, l1;
                        split2(v.x, v.y, h0, l0);
                        split2(v.z, v.w, h1, l1);
                        *(uint2*)(ahi + i * 8) = make_uint2(h0, h1);
                        *(uint2*)(alo + i * 8) = make_uint2(l0, l1);
                    }
                }
                __syncthreads();

                // ---- GEMM over K=256 in 16-wide steps ----
                #pragma unroll 4
                for (int kk = 0; kk < 16; kk++) {
                    const uint32_t ka = kk * 32;
                    uint32_t ah[4], al[4];
                    ldm_x4(ah[0], ah[1], ah[2], ah[3], smb + SM_A_HI + a_off + ka);
                    ldm_x4(al[0], al[1], al[2], al[3], smb + SM_A_LO + a_off + ka);
                    uint32_t bh[8], bl[8];
                    ldm_x4(bh[0], bh[1], bh[2], bh[3], smb + SM_W_HI + b_off + ka);
                    ldm_x4(bh[4], bh[5], bh[6], bh[7], smb + SM_W_HI + 16 * PITCH + b_off + ka);
                    ldm_x4(bl[0], bl[1], bl[2], bl[3], smb + SM_W_LO + b_off + ka);
                    ldm_x4(bl[4], bl[5], bl[6], bl[7], smb + SM_W_LO + 16 * PITCH + b_off + ka);
                    // groups: g0=(r0,r2) rows 0-7, g1=(r1,r3) rows 8-15 (per 16-row ldm)
                    mma_bf16(acc[0], ah, bh[0], bh[2]);
                    mma_bf16(acc[1], ah, bh[1], bh[3]);
                    mma_bf16(acc[2], ah, bh[4], bh[6]);
                    mma_bf16(acc[3], ah, bh[5], bh[7]);
                    mma_bf16(acc[0], ah, bl[0], bl[2]);
                    mma_bf16(acc[1], ah, bl[1], bl[3]);
                    mma_bf16(acc[2], ah, bl[4], bl[6]);
                    mma_bf16(acc[3], ah, bl[5], bl[7]);
                    mma_bf16(acc[0], al, bh[0], bh[2]);
                    mma_bf16(acc[1], al, bh[1], bh[3]);
                    mma_bf16(acc[2], al, bh[4], bh[6]);
                    mma_bf16(acc[3], al, bh[5], bh[7]);
                }
            }

            // ---- epilogue ----
            // Thread pair (q, q^1) shares jt; bfly reunites all 4 gate types.
            // even q: has (i,f) rows rr,rr+8 -> computes row rr
            // odd  q: has (g,o) rows rr,rr+8 -> computes row rr+8
            const size_t s_cur  = (size_t)cell_id * NB * HID;
            const size_t s_up   = (size_t)(cell_id - HW) * NB * HID;
            const size_t s_left = (size_t)(cell_id - 1) * NB * HID;
            const float xp = x[b_ep * (HW * HW) + cell_id];

            #pragma unroll
            for (int g = 0; g < 4; g++) {
                const int jt = nh * 8 + g * 2 + (q >> 1);
                const int j  = sb * 16 + jt;

                const float send0 = p ? acc[g][0] : acc[g][2];
                const float send1 = p ? acc[g][1] : acc[g][3];
                const float recv0 = __shfl_xor_sync(0xFFFFFFFFu, send0, 1);
                const float recv1 = __shfl_xor_sync(0xFFFFFFFFu, send1, 1);

                const float gi = p ? recv0     : acc[g][0];
                const float gf = p ? recv1     : acc[g][1];
                const float gg = p ? acc[g][2] : recv0;
                const float go = p ? acc[g][3] : recv1;

                const float vi = gi + sbias[jt]      + xp * swih[jt];
                const float vf = gf + sbias[16 + jt] + xp * swih[16 + jt];
                const float vg = gg + sbias[32 + jt] + xp * swih[32 + jt];
                const float vo = go + sbias[48 + jt] + xp * swih[48 + jt];

                const float iv = sigmoidf_(vi);
                const float fv = sigmoidf_(vf);
                const float gv = tanhf(vg);
                const float ov = sigmoidf_(vo);

                float ssum = 0.0f;
                if (has_up)   ssum += g_s[s_up   + (size_t)b_ep * HID + j];
                if (has_left) ssum += g_s[s_left + (size_t)b_ep * HID + j];

                const float sv = fv * ssum + iv * gv;
                const float hv = ov * tanhf(sv);

                g_s[s_cur + (size_t)b_ep * HID + j] = sv;
                out[(size_t)b_ep * (HW * HW * HID) + (size_t)cell_id * HID + j] = hv;
            }
            __syncthreads();   // all warps done with smem A before next staging
        }
        grid_barrier();
    }
}

extern "C" void kernel_launch(void* const* d_in, const int* in_sizes, int n_in,
                              void* d_out, int out_size) {
    const float* x    = (const float*)d_in[0];
    const float* w_ih = (const float*)d_in[1];
    const float* w_hh = (const float*)d_in[2];
    const float* bias = (const float*)d_in[3];
    float* out = (float*)d_out;

    cudaFuncSetAttribute(mdlstm_mma,
                         cudaFuncAttributeMaxDynamicSharedMemorySize, SMEM_TOTAL);
    mdlstm_mma<<<NBLK, THREADS, SMEM_TOTAL>>>(x, w_ih, w_hh, bias, out);
}